// round 2
// baseline (speedup 1.0000x reference)
#include <cuda_runtime.h>
#include <math.h>

#define BB   16
#define INC  1024
#define PP   256
#define NHEAD 4
#define DD   64
#define NNL  1024     // N = W*H
#define WW   32
#define HHS  32

// ---------------- scratch (device globals: no runtime allocation) ----------------
__device__ float g_ds [(size_t)BB*PP*NNL];
__device__ float g_q  [(size_t)BB*PP*NNL];
__device__ float g_k  [(size_t)BB*PP*NNL];
__device__ float g_v  [(size_t)BB*PP*NNL];
__device__ float g_o  [(size_t)BB*PP*NNL];
__device__ float g_y  [(size_t)BB*PP*NNL];
__device__ float g_pos[(size_t)NHEAD*DD*NNL];
__device__ float g_attn[(size_t)BB*NHEAD*NNL*NNL];   // 256 MB

// ---------------- pos = rel_h + rel_w, flattened [h][d][n], n = w*32 + hh --------
__global__ void k_pos(const float* __restrict__ rel_h, const float* __restrict__ rel_w) {
    int idx = blockIdx.x * 256 + threadIdx.x;           // over NHEAD*DD*NNL
    if (idx >= NHEAD * DD * NNL) return;
    int n  = idx & (NNL - 1);
    int hd = idx >> 10;                                 // h*DD + d
    int w  = n >> 5, hh = n & 31;
    g_pos[idx] = rel_h[hd * HHS + hh] + rel_w[hd * WW + w];
}

// ---------------- downsample conv: g_ds[b] = w_ds(256x1024) @ x_b(1024x1024) -----
__global__ void __launch_bounds__(256) k_ds(const float* __restrict__ x,
                                            const float* __restrict__ w) {
    const int b = blockIdx.z;
    const float* A  = w;
    const float* Bm = x + (size_t)b * INC * NNL;
    float* C = g_ds + (size_t)b * PP * NNL;

    __shared__ float As[8][128];
    __shared__ float Bs[8][128];
    const int tid = threadIdx.x;
    const int m0 = blockIdx.y * 128, n0 = blockIdx.x * 128;
    const int a_m = tid >> 1, a_k = (tid & 1) * 4;
    const int b_k = tid >> 5, b_n = (tid & 31) * 4;
    const int tx = tid & 15, ty = tid >> 4;
    float acc[8][8] = {};

    for (int k0 = 0; k0 < INC; k0 += 8) {
        float4 av = *(const float4*)(A + (size_t)(m0 + a_m) * INC + k0 + a_k);
        As[a_k + 0][a_m] = av.x; As[a_k + 1][a_m] = av.y;
        As[a_k + 2][a_m] = av.z; As[a_k + 3][a_m] = av.w;
        *(float4*)&Bs[b_k][b_n] = *(const float4*)(Bm + (size_t)(k0 + b_k) * NNL + n0 + b_n);
        __syncthreads();
#pragma unroll
        for (int kk = 0; kk < 8; kk++) {
            float4 a0 = *(float4*)&As[kk][ty * 4];
            float4 a1 = *(float4*)&As[kk][64 + ty * 4];
            float4 b0 = *(float4*)&Bs[kk][tx * 4];
            float4 b1 = *(float4*)&Bs[kk][64 + tx * 4];
            float af[8] = {a0.x,a0.y,a0.z,a0.w,a1.x,a1.y,a1.z,a1.w};
            float bf[8] = {b0.x,b0.y,b0.z,b0.w,b1.x,b1.y,b1.z,b1.w};
#pragma unroll
            for (int i = 0; i < 8; i++)
#pragma unroll
                for (int j = 0; j < 8; j++) acc[i][j] = fmaf(af[i], bf[j], acc[i][j]);
        }
        __syncthreads();
    }
#pragma unroll
    for (int i = 0; i < 8; i++) {
        int m = m0 + ((i < 4) ? (ty * 4 + i) : (64 + ty * 4 + i - 4));
#pragma unroll
        for (int j = 0; j < 8; j++) {
            int n = n0 + ((j < 4) ? (tx * 4 + j) : (64 + tx * 4 + j - 4));
            C[(size_t)m * NNL + n] = acc[i][j];
        }
    }
}

// ---------------- q/k/v: W(256x256) @ g_ds_b + bias ------------------------------
__global__ void __launch_bounds__(256) k_qkv(const float* __restrict__ wq,
                                             const float* __restrict__ wk,
                                             const float* __restrict__ wv,
                                             const float* __restrict__ bq,
                                             const float* __restrict__ bk,
                                             const float* __restrict__ bv) {
    const int z = blockIdx.z;
    const int which = z / BB;
    const int b = z % BB;
    const float* A    = (which == 0) ? wq : (which == 1) ? wk : wv;
    const float* bias = (which == 0) ? bq : (which == 1) ? bk : bv;
    const float* Bm = g_ds + (size_t)b * PP * NNL;
    float* C = ((which == 0) ? g_q : (which == 1) ? g_k : g_v) + (size_t)b * PP * NNL;

    __shared__ float As[8][128];
    __shared__ float Bs[8][128];
    const int tid = threadIdx.x;
    const int m0 = blockIdx.y * 128, n0 = blockIdx.x * 128;
    const int a_m = tid >> 1, a_k = (tid & 1) * 4;
    const int b_k = tid >> 5, b_n = (tid & 31) * 4;
    const int tx = tid & 15, ty = tid >> 4;
    float acc[8][8] = {};

    for (int k0 = 0; k0 < PP; k0 += 8) {
        float4 av = *(const float4*)(A + (size_t)(m0 + a_m) * PP + k0 + a_k);
        As[a_k + 0][a_m] = av.x; As[a_k + 1][a_m] = av.y;
        As[a_k + 2][a_m] = av.z; As[a_k + 3][a_m] = av.w;
        *(float4*)&Bs[b_k][b_n] = *(const float4*)(Bm + (size_t)(k0 + b_k) * NNL + n0 + b_n);
        __syncthreads();
#pragma unroll
        for (int kk = 0; kk < 8; kk++) {
            float4 a0 = *(float4*)&As[kk][ty * 4];
            float4 a1 = *(float4*)&As[kk][64 + ty * 4];
            float4 b0 = *(float4*)&Bs[kk][tx * 4];
            float4 b1 = *(float4*)&Bs[kk][64 + tx * 4];
            float af[8] = {a0.x,a0.y,a0.z,a0.w,a1.x,a1.y,a1.z,a1.w};
            float bf[8] = {b0.x,b0.y,b0.z,b0.w,b1.x,b1.y,b1.z,b1.w};
#pragma unroll
            for (int i = 0; i < 8; i++)
#pragma unroll
                for (int j = 0; j < 8; j++) acc[i][j] = fmaf(af[i], bf[j], acc[i][j]);
        }
        __syncthreads();
    }
#pragma unroll
    for (int i = 0; i < 8; i++) {
        int m = m0 + ((i < 4) ? (ty * 4 + i) : (64 + ty * 4 + i - 4));
        float bb = bias[m];
#pragma unroll
        for (int j = 0; j < 8; j++) {
            int n = n0 + ((j < 4) ? (tx * 4 + j) : (64 + tx * 4 + j - 4));
            C[(size_t)m * NNL + n] = acc[i][j] + bb;
        }
    }
}

// ---- logits[i,j] = sum_d q[d,i]k[d,j] + sum_d pos[d,i]q[d,j]  (one GEMM, K=128) --
__global__ void __launch_bounds__(256) k_logits() {
    const int z = blockIdx.z;                // b*NHEAD + h
    const int b = z >> 2, h = z & 3;
    const float* qp = g_q + (size_t)(b * NHEAD + h) * DD * NNL;
    const float* kp = g_k + (size_t)(b * NHEAD + h) * DD * NNL;
    const float* pp = g_pos + (size_t)h * DD * NNL;
    float* C = g_attn + (size_t)z * NNL * NNL;

    __shared__ float As[8][128];
    __shared__ float Bs[8][128];
    const int tid = threadIdx.x;
    const int m0 = blockIdx.y * 128, n0 = blockIdx.x * 128;
    const int l_k = tid >> 5, l_m = (tid & 31) * 4;
    const int tx = tid & 15, ty = tid >> 4;
    float acc[8][8] = {};

    for (int k0 = 0; k0 < 2 * DD; k0 += 8) {
        int d = k0 + l_k;
        const float* arow = (d < DD) ? (qp + (size_t)d * NNL) : (pp + (size_t)(d - DD) * NNL);
        const float* brow = (d < DD) ? (kp + (size_t)d * NNL) : (qp + (size_t)(d - DD) * NNL);
        *(float4*)&As[l_k][l_m] = *(const float4*)(arow + m0 + l_m);
        *(float4*)&Bs[l_k][l_m] = *(const float4*)(brow + n0 + l_m);
        __syncthreads();
#pragma unroll
        for (int kk = 0; kk < 8; kk++) {
            float4 a0 = *(float4*)&As[kk][ty * 4];
            float4 a1 = *(float4*)&As[kk][64 + ty * 4];
            float4 b0 = *(float4*)&Bs[kk][tx * 4];
            float4 b1 = *(float4*)&Bs[kk][64 + tx * 4];
            float af[8] = {a0.x,a0.y,a0.z,a0.w,a1.x,a1.y,a1.z,a1.w};
            float bf[8] = {b0.x,b0.y,b0.z,b0.w,b1.x,b1.y,b1.z,b1.w};
#pragma unroll
            for (int i = 0; i < 8; i++)
#pragma unroll
                for (int j = 0; j < 8; j++) acc[i][j] = fmaf(af[i], bf[j], acc[i][j]);
        }
        __syncthreads();
    }
#pragma unroll
    for (int i = 0; i < 8; i++) {
        int m = m0 + ((i < 4) ? (ty * 4 + i) : (64 + ty * 4 + i - 4));
#pragma unroll
        for (int j = 0; j < 8; j++) {
            int n = n0 + ((j < 4) ? (tx * 4 + j) : (64 + tx * 4 + j - 4));
            C[(size_t)m * NNL + n] = acc[i][j];
        }
    }
}

// ---------------- row softmax over j (1024), one block per row -------------------
__global__ void __launch_bounds__(256) k_softmax() {
    const size_t row = blockIdx.x;
    float* r = g_attn + row * NNL;
    const int tid = threadIdx.x;
    float4 v = ((float4*)r)[tid];

    __shared__ float red[8];
    float lm = fmaxf(fmaxf(v.x, v.y), fmaxf(v.z, v.w));
#pragma unroll
    for (int o = 16; o > 0; o >>= 1) lm = fmaxf(lm, __shfl_xor_sync(~0u, lm, o));
    if ((tid & 31) == 0) red[tid >> 5] = lm;
    __syncthreads();
    if (tid < 32) {
        float t = (tid < 8) ? red[tid] : -INFINITY;
#pragma unroll
        for (int o = 4; o > 0; o >>= 1) t = fmaxf(t, __shfl_xor_sync(~0u, t, o));
        if (tid == 0) red[0] = t;
    }
    __syncthreads();
    const float m = red[0];
    __syncthreads();

    v.x = expf(v.x - m); v.y = expf(v.y - m);
    v.z = expf(v.z - m); v.w = expf(v.w - m);
    float s = v.x + v.y + v.z + v.w;
#pragma unroll
    for (int o = 16; o > 0; o >>= 1) s += __shfl_xor_sync(~0u, s, o);
    if ((tid & 31) == 0) red[tid >> 5] = s;
    __syncthreads();
    if (tid < 32) {
        float t = (tid < 8) ? red[tid] : 0.f;
#pragma unroll
        for (int o = 4; o > 0; o >>= 1) t += __shfl_xor_sync(~0u, t, o);
        if (tid == 0) red[0] = t;
    }
    __syncthreads();
    const float inv = 1.f / red[0];
    v.x *= inv; v.y *= inv; v.z *= inv; v.w *= inv;
    ((float4*)r)[tid] = v;
}

// ---------------- o[d,i] = sum_j v[d,j] * attn[i,j]   (64 x 1024, K=1024) --------
__global__ void __launch_bounds__(256) k_av() {
    const int z = blockIdx.z;
    const int b = z >> 2, h = z & 3;
    const float* V  = g_v + (size_t)(b * NHEAD + h) * DD * NNL;
    const float* At = g_attn + (size_t)z * NNL * NNL;
    float* C = g_o + ((size_t)b * PP + (size_t)h * DD) * NNL;

    __shared__ float As[16][65];     // v^T tile   [k][m], padded
    __shared__ float Bs[16][129];    // attn tile  [k][n], padded
    const int tid = threadIdx.x;
    const int n0 = blockIdx.x * 128;
    const int a_m = tid >> 2, a_k = (tid & 3) * 4;
    const int tx = tid & 15, ty = tid >> 4;
    float acc[4][8] = {};

    for (int k0 = 0; k0 < NNL; k0 += 16) {
        float4 av = *(const float4*)(V + (size_t)a_m * NNL + k0 + a_k);
        As[a_k + 0][a_m] = av.x; As[a_k + 1][a_m] = av.y;
        As[a_k + 2][a_m] = av.z; As[a_k + 3][a_m] = av.w;
#pragma unroll
        for (int r = 0; r < 2; r++) {
            int n = a_m + r * 64;
            float4 bv = *(const float4*)(At + (size_t)(n0 + n) * NNL + k0 + a_k);
            Bs[a_k + 0][n] = bv.x; Bs[a_k + 1][n] = bv.y;
            Bs[a_k + 2][n] = bv.z; Bs[a_k + 3][n] = bv.w;
        }
        __syncthreads();
#pragma unroll
        for (int kk = 0; kk < 16; kk++) {
            float af[4], bf[8];
#pragma unroll
            for (int i = 0; i < 4; i++) af[i] = As[kk][ty * 4 + i];
#pragma unroll
            for (int j = 0; j < 4; j++) { bf[j] = Bs[kk][tx * 4 + j]; bf[4 + j] = Bs[kk][64 + tx * 4 + j]; }
#pragma unroll
            for (int i = 0; i < 4; i++)
#pragma unroll
                for (int j = 0; j < 8; j++) acc[i][j] = fmaf(af[i], bf[j], acc[i][j]);
        }
        __syncthreads();
    }
#pragma unroll
    for (int i = 0; i < 4; i++) {
        int m = ty * 4 + i;
#pragma unroll
        for (int j = 0; j < 8; j++) {
            int n = n0 + ((j < 4) ? (tx * 4 + j) : (64 + tx * 4 + j - 4));
            C[(size_t)m * NNL + n] = acc[i][j];
        }
    }
}

// ---------------- LayerNorm over channels P at each (b, n) -----------------------
__global__ void __launch_bounds__(256) k_ln(const float* __restrict__ lw,
                                            const float* __restrict__ lb) {
    const int b = blockIdx.y;
    const int tx = threadIdx.x & 31;
    const int ty = threadIdx.x >> 5;                     // 0..7
    const int n = blockIdx.x * 32 + tx;
    const float* op = g_o + (size_t)b * PP * NNL + n;
    float* yp = g_y + (size_t)b * PP * NNL + n;

    float vals[32];
    float s = 0.f, s2 = 0.f;
#pragma unroll
    for (int i = 0; i < 32; i++) {
        float v = op[(size_t)(ty + 8 * i) * NNL];
        vals[i] = v; s += v; s2 += v * v;
    }
    __shared__ float rs[8][32], rq[8][32];
    rs[ty][tx] = s; rq[ty][tx] = s2;
    __syncthreads();
    if (ty == 0) {
        float a = 0.f, c = 0.f;
#pragma unroll
        for (int i = 0; i < 8; i++) { a += rs[i][tx]; c += rq[i][tx]; }
        rs[0][tx] = a; rq[0][tx] = c;
    }
    __syncthreads();
    const float mean = rs[0][tx] * (1.f / 256.f);
    const float var  = rq[0][tx] * (1.f / 256.f) - mean * mean;
    const float rstd = rsqrtf(var + 1e-6f);
#pragma unroll
    for (int i = 0; i < 32; i++) {
        int p = ty + 8 * i;
        yp[(size_t)p * NNL] = (vals[i] - mean) * rstd * lw[p] + lb[p];
    }
}

// ---------------- expand conv + exact GELU + residual ----------------------------
__global__ void __launch_bounds__(256) k_expand(const float* __restrict__ w1,
                                                const float* __restrict__ x,
                                                float* __restrict__ out) {
    const int b = blockIdx.z;
    const float* A  = w1;                                // [1024, 256]
    const float* Bm = g_y + (size_t)b * PP * NNL;
    const float* xr = x   + (size_t)b * INC * NNL;
    float* C = out + (size_t)b * INC * NNL;

    __shared__ float As[8][128];
    __shared__ float Bs[8][128];
    const int tid = threadIdx.x;
    const int m0 = blockIdx.y * 128, n0 = blockIdx.x * 128;
    const int a_m = tid >> 1, a_k = (tid & 1) * 4;
    const int b_k = tid >> 5, b_n = (tid & 31) * 4;
    const int tx = tid & 15, ty = tid >> 4;
    float acc[8][8] = {};

    for (int k0 = 0; k0 < PP; k0 += 8) {
        float4 av = *(const float4*)(A + (size_t)(m0 + a_m) * PP + k0 + a_k);
        As[a_k + 0][a_m] = av.x; As[a_k + 1][a_m] = av.y;
        As[a_k + 2][a_m] = av.z; As[a_k + 3][a_m] = av.w;
        *(float4*)&Bs[b_k][b_n] = *(const float4*)(Bm + (size_t)(k0 + b_k) * NNL + n0 + b_n);
        __syncthreads();
#pragma unroll
        for (int kk = 0; kk < 8; kk++) {
            float4 a0 = *(float4*)&As[kk][ty * 4];
            float4 a1 = *(float4*)&As[kk][64 + ty * 4];
            float4 b0 = *(float4*)&Bs[kk][tx * 4];
            float4 b1 = *(float4*)&Bs[kk][64 + tx * 4];
            float af[8] = {a0.x,a0.y,a0.z,a0.w,a1.x,a1.y,a1.z,a1.w};
            float bf[8] = {b0.x,b0.y,b0.z,b0.w,b1.x,b1.y,b1.z,b1.w};
#pragma unroll
            for (int i = 0; i < 8; i++)
#pragma unroll
                for (int j = 0; j < 8; j++) acc[i][j] = fmaf(af[i], bf[j], acc[i][j]);
        }
        __syncthreads();
    }
#pragma unroll
    for (int i = 0; i < 8; i++) {
        int m = m0 + ((i < 4) ? (ty * 4 + i) : (64 + ty * 4 + i - 4));
#pragma unroll
        for (int j = 0; j < 8; j++) {
            int n = n0 + ((j < 4) ? (tx * 4 + j) : (64 + tx * 4 + j - 4));
            float t = acc[i][j];
            float g = t * normcdff(t);                   // exact GELU
            C[(size_t)m * NNL + n] = g + xr[(size_t)m * NNL + n];
        }
    }
}

// ---------------- launch --------------------------------------------------------
extern "C" void kernel_launch(void* const* d_in, const int* in_sizes, int n_in,
                              void* d_out, int out_size) {
    const float* x     = (const float*)d_in[0];
    const float* w_ds  = (const float*)d_in[1];
    const float* wq    = (const float*)d_in[2];
    const float* bq    = (const float*)d_in[3];
    const float* wk    = (const float*)d_in[4];
    const float* bk    = (const float*)d_in[5];
    const float* wv    = (const float*)d_in[6];
    const float* bv    = (const float*)d_in[7];
    const float* rel_h = (const float*)d_in[8];
    const float* rel_w = (const float*)d_in[9];
    const float* ln_w  = (const float*)d_in[10];
    const float* ln_b  = (const float*)d_in[11];
    const float* w1    = (const float*)d_in[12];
    float* out = (float*)d_out;

    k_pos    <<<(NHEAD * DD * NNL + 255) / 256, 256>>>(rel_h, rel_w);
    k_ds     <<<dim3(8, 2, BB), 256>>>(x, w_ds);
    k_qkv    <<<dim3(8, 2, 3 * BB), 256>>>(wq, wk, wv, bq, bk, bv);
    k_logits <<<dim3(8, 8, BB * NHEAD), 256>>>();
    k_softmax<<<BB * NHEAD * NNL, 256>>>();
    k_av     <<<dim3(8, 1, BB * NHEAD), 256>>>();
    k_ln     <<<dim3(NNL / 32, BB), 256>>>(ln_w, ln_b);
    k_expand <<<dim3(8, 8, BB), 256>>>(w1, x, out);
}

// round 16
// speedup vs baseline: 1.7617x; 1.7617x over previous
#include <cuda_runtime.h>
#include <cuda_bf16.h>
#include <math.h>

#define BB   16
#define INC  1024
#define PP   256
#define NHEAD 4
#define DD   64
#define NNL  1024
#define WW   32
#define HHS  32

// ---------------- scratch (device globals) ----------------
__device__ float g_ds2 [(size_t)BB*NNL*PP];          // [b][n][p]
__device__ float g_q2  [(size_t)BB*NNL*PP];          // [b][i][p]
__device__ float g_k2  [(size_t)BB*NNL*PP];          // [b][j][p]
__device__ float g_v   [(size_t)BB*PP*NNL];          // [b][p][j]
__device__ float g_pos2[(size_t)NHEAD*NNL*DD];       // [h][n][d]
__device__ float g_attn[(size_t)BB*NHEAD*NNL*NNL];   // [b,h][i][j]
__device__ float g_o2  [(size_t)BB*NNL*PP];          // [b][i][p]
__device__ float g_y2  [(size_t)BB*NNL*PP];          // [b][i][p]

// ---------------- mma wrapper ----------------
__device__ __forceinline__ void mma_bf16(float* d, const unsigned* a, const unsigned* b) {
    asm volatile(
        "mma.sync.aligned.m16n8k16.row.col.f32.bf16.bf16.f32 "
        "{%0,%1,%2,%3}, {%4,%5,%6,%7}, {%8,%9}, {%0,%1,%2,%3};\n"
        : "+f"(d[0]), "+f"(d[1]), "+f"(d[2]), "+f"(d[3])
        : "r"(a[0]), "r"(a[1]), "r"(a[2]), "r"(a[3]), "r"(b[0]), "r"(b[1]));
}

// ---------------- smem hi/lo store of a float4 ----------------
__device__ __forceinline__ void st_hl(__nv_bfloat16 (*Sh)[36], __nv_bfloat16 (*Sl)[36],
                                      int r, int c4, float4 v) {
    __nv_bfloat16 h0 = __float2bfloat16(v.x), h1 = __float2bfloat16(v.y);
    __nv_bfloat16 h2 = __float2bfloat16(v.z), h3 = __float2bfloat16(v.w);
    __nv_bfloat16 l0 = __float2bfloat16(v.x - __bfloat162float(h0));
    __nv_bfloat16 l1 = __float2bfloat16(v.y - __bfloat162float(h1));
    __nv_bfloat16 l2 = __float2bfloat16(v.z - __bfloat162float(h2));
    __nv_bfloat16 l3 = __float2bfloat16(v.w - __bfloat162float(h3));
    *(__nv_bfloat162*)&Sh[r][c4]     = __halves2bfloat162(h0, h1);
    *(__nv_bfloat162*)&Sh[r][c4 + 2] = __halves2bfloat162(h2, h3);
    *(__nv_bfloat162*)&Sl[r][c4]     = __halves2bfloat162(l0, l1);
    *(__nv_bfloat162*)&Sl[r][c4 + 2] = __halves2bfloat162(l2, l3);
}

// direct tile loader: ROWS x 32 fp32 tile, gmem row-major stride ld
template<int ROWS>
__device__ __forceinline__ void ld_direct(const float* g, size_t ld,
                                          __nv_bfloat16 (*Sh)[36], __nv_bfloat16 (*Sl)[36],
                                          int tid) {
    int r0 = tid >> 3, c4 = (tid & 7) * 4;
#pragma unroll
    for (int i = 0; i < ROWS / 32; i++) {
        int r = r0 + 32 * i;
        float4 v = *(const float4*)(g + (size_t)r * ld + c4);
        st_hl(Sh, Sl, r, c4, v);
    }
}

// core warp-tile mma over one BK=32 smem tile
template<int MT, int NT>
__device__ __forceinline__ void mma_tile(float acc[MT][NT][4],
                                         const __nv_bfloat16 (*Ah)[36], const __nv_bfloat16 (*Al)[36],
                                         const __nv_bfloat16 (*Bh)[36], const __nv_bfloat16 (*Bl)[36],
                                         int wm, int wn, int gr, int gc) {
#pragma unroll
    for (int ks = 0; ks < 2; ks++) {
        const int ko = ks * 8;
        unsigned bh[NT][2], bl[NT][2];
#pragma unroll
        for (int nt = 0; nt < NT; nt++) {
            const unsigned* rh = (const unsigned*)&Bh[wn + nt * 8 + gr][0];
            const unsigned* rl = (const unsigned*)&Bl[wn + nt * 8 + gr][0];
            bh[nt][0] = rh[ko + gc]; bh[nt][1] = rh[ko + gc + 4];
            bl[nt][0] = rl[ko + gc]; bl[nt][1] = rl[ko + gc + 4];
        }
#pragma unroll
        for (int mt = 0; mt < MT; mt++) {
            const unsigned* r0h = (const unsigned*)&Ah[wm + mt * 16 + gr][0];
            const unsigned* r1h = (const unsigned*)&Ah[wm + mt * 16 + 8 + gr][0];
            const unsigned* r0l = (const unsigned*)&Al[wm + mt * 16 + gr][0];
            const unsigned* r1l = (const unsigned*)&Al[wm + mt * 16 + 8 + gr][0];
            unsigned ah[4] = {r0h[ko + gc], r1h[ko + gc], r0h[ko + gc + 4], r1h[ko + gc + 4]};
            unsigned al[4] = {r0l[ko + gc], r1l[ko + gc], r0l[ko + gc + 4], r1l[ko + gc + 4]};
#pragma unroll
            for (int nt = 0; nt < NT; nt++) {
                mma_bf16(acc[mt][nt], ah, bh[nt]);
                mma_bf16(acc[mt][nt], ah, bl[nt]);
                mma_bf16(acc[mt][nt], al, bh[nt]);
            }
        }
    }
}

// ---------------- pos2[h][n][d] = rel_h + rel_w ----------------
__global__ void k_pos(const float* __restrict__ rel_h, const float* __restrict__ rel_w) {
    int idx = blockIdx.x * 256 + threadIdx.x;            // over NHEAD*NNL*DD
    if (idx >= NHEAD * NNL * DD) return;
    int d = idx & (DD - 1);
    int n = (idx >> 6) & (NNL - 1);
    int h = idx >> 16;
    int w = n >> 5, hh = n & 31;
    g_pos2[idx] = rel_h[(h * DD + d) * HHS + hh] + rel_w[(h * DD + d) * WW + w];
}

// ---------------- k_ds: ds2[b][n][p] = (w_ds @ x_b)^T ----------------
__global__ void __launch_bounds__(256) k_ds(const float* __restrict__ x,
                                            const float* __restrict__ w) {
    const int b = blockIdx.z;
    __shared__ __nv_bfloat16 Ah[128][36], Al[128][36], Bh[128][36], Bl[128][36];
    const int tid = threadIdx.x, wid = tid >> 5, lane = tid & 31;
    const int wm = (wid >> 1) * 32, wn = (wid & 1) * 64, gr = lane >> 2, gc = lane & 3;
    const int m0 = blockIdx.y * 128, n0 = blockIdx.x * 128;
    float acc[2][8][4] = {};
    const float* xb = x + (size_t)b * INC * NNL;

    for (int k0 = 0; k0 < INC; k0 += 32) {
        ld_direct<128>(w + (size_t)m0 * INC + k0, INC, Ah, Al, tid);
        // transpose-load B: x[c][n] -> Bs[n][c]
        {
            int c = tid >> 3;
#pragma unroll
            for (int i = 0; i < 4; i++) {
                int n4 = (tid & 7) + 8 * i;
                float4 v = *(const float4*)(xb + (size_t)(k0 + c) * NNL + n0 + n4 * 4);
                float f[4] = {v.x, v.y, v.z, v.w};
#pragma unroll
                for (int j = 0; j < 4; j++) {
                    __nv_bfloat16 h = __float2bfloat16(f[j]);
                    Bh[n4 * 4 + j][c] = h;
                    Bl[n4 * 4 + j][c] = __float2bfloat16(f[j] - __bfloat162float(h));
                }
            }
        }
        __syncthreads();
        mma_tile<2, 8>(acc, Ah, Al, Bh, Bl, wm, wn, gr, gc);
        __syncthreads();
    }
    // transposed store -> ds2[b][n][m]
    float* C = g_ds2 + (size_t)b * NNL * PP;
#pragma unroll
    for (int mt = 0; mt < 2; mt++)
#pragma unroll
        for (int nt = 0; nt < 8; nt++) {
            int m = m0 + wm + mt * 16 + gr;
            int n = n0 + wn + nt * 8 + gc * 2;
            C[(size_t)n * PP + m]           = acc[mt][nt][0];
            C[(size_t)(n + 1) * PP + m]     = acc[mt][nt][1];
            C[(size_t)n * PP + m + 8]       = acc[mt][nt][2];
            C[(size_t)(n + 1) * PP + m + 8] = acc[mt][nt][3];
        }
}

// ---------------- k_qkv ----------------
__global__ void __launch_bounds__(256) k_qkv(const float* __restrict__ wq,
                                             const float* __restrict__ wk,
                                             const float* __restrict__ wv,
                                             const float* __restrict__ bq,
                                             const float* __restrict__ bk,
                                             const float* __restrict__ bv) {
    const int z = blockIdx.z;
    const int which = z / BB, b = z % BB;
    const float* A    = (which == 0) ? wq : (which == 1) ? wk : wv;
    const float* bias = (which == 0) ? bq : (which == 1) ? bk : bv;
    __shared__ __nv_bfloat16 Ah[128][36], Al[128][36], Bh[128][36], Bl[128][36];
    const int tid = threadIdx.x, wid = tid >> 5, lane = tid & 31;
    const int wm = (wid >> 1) * 32, wn = (wid & 1) * 64, gr = lane >> 2, gc = lane & 3;
    const int m0 = blockIdx.y * 128, n0 = blockIdx.x * 128;
    float acc[2][8][4] = {};
    const float* Bg = g_ds2 + (size_t)b * NNL * PP;

    for (int k0 = 0; k0 < PP; k0 += 32) {
        ld_direct<128>(A + (size_t)m0 * PP + k0, PP, Ah, Al, tid);
        ld_direct<128>(Bg + (size_t)n0 * PP + k0, PP, Bh, Bl, tid);
        __syncthreads();
        mma_tile<2, 8>(acc, Ah, Al, Bh, Bl, wm, wn, gr, gc);
        __syncthreads();
    }
    if (which < 2) {
        float* C = ((which == 0) ? g_q2 : g_k2) + (size_t)b * NNL * PP;
#pragma unroll
        for (int mt = 0; mt < 2; mt++)
#pragma unroll
            for (int nt = 0; nt < 8; nt++) {
                int m = m0 + wm + mt * 16 + gr;
                int n = n0 + wn + nt * 8 + gc * 2;
                float b0v = bias[m], b8v = bias[m + 8];
                C[(size_t)n * PP + m]           = acc[mt][nt][0] + b0v;
                C[(size_t)(n + 1) * PP + m]     = acc[mt][nt][1] + b0v;
                C[(size_t)n * PP + m + 8]       = acc[mt][nt][2] + b8v;
                C[(size_t)(n + 1) * PP + m + 8] = acc[mt][nt][3] + b8v;
            }
    } else {
        float* C = g_v + (size_t)b * PP * NNL;
#pragma unroll
        for (int mt = 0; mt < 2; mt++)
#pragma unroll
            for (int nt = 0; nt < 8; nt++) {
                int m = m0 + wm + mt * 16 + gr;
                int n = n0 + wn + nt * 8 + gc * 2;
                float b0v = bias[m], b8v = bias[m + 8];
                float2 r0 = {acc[mt][nt][0] + b0v, acc[mt][nt][1] + b0v};
                float2 r1 = {acc[mt][nt][2] + b8v, acc[mt][nt][3] + b8v};
                *(float2*)&C[(size_t)m * NNL + n]       = r0;
                *(float2*)&C[(size_t)(m + 8) * NNL + n] = r1;
            }
    }
}

// ---------------- k_logits: attn[i][j] = q_i.k_j + pos_i.q_j  (K=128) ----------------
__global__ void __launch_bounds__(256) k_logits() {
    const int z = blockIdx.z;
    const int b = z >> 2, h = z & 3;
    __shared__ __nv_bfloat16 Ah[128][36], Al[128][36], Bh[128][36], Bl[128][36];
    const int tid = threadIdx.x, wid = tid >> 5, lane = tid & 31;
    const int wm = (wid >> 1) * 32, wn = (wid & 1) * 64, gr = lane >> 2, gc = lane & 3;
    const int m0 = blockIdx.y * 128, n0 = blockIdx.x * 128;
    float acc[2][8][4] = {};

    for (int k0 = 0; k0 < 128; k0 += 32) {
        if (k0 < 64) {
            ld_direct<128>(g_q2 + ((size_t)(b * NNL) + m0) * PP + h * DD + k0, PP, Ah, Al, tid);
            ld_direct<128>(g_k2 + ((size_t)(b * NNL) + n0) * PP + h * DD + k0, PP, Bh, Bl, tid);
        } else {
            ld_direct<128>(g_pos2 + ((size_t)(h * NNL) + m0) * DD + (k0 - 64), DD, Ah, Al, tid);
            ld_direct<128>(g_q2 + ((size_t)(b * NNL) + n0) * PP + h * DD + (k0 - 64), PP, Bh, Bl, tid);
        }
        __syncthreads();
        mma_tile<2, 8>(acc, Ah, Al, Bh, Bl, wm, wn, gr, gc);
        __syncthreads();
    }
    float* C = g_attn + (size_t)z * NNL * NNL;
#pragma unroll
    for (int mt = 0; mt < 2; mt++)
#pragma unroll
        for (int nt = 0; nt < 8; nt++) {
            int m = m0 + wm + mt * 16 + gr;
            int n = n0 + wn + nt * 8 + gc * 2;
            *(float2*)&C[(size_t)m * NNL + n]       = *(float2*)&acc[mt][nt][0];
            *(float2*)&C[(size_t)(m + 8) * NNL + n] = *(float2*)&acc[mt][nt][2];
        }
}

// ---------------- row softmax ----------------
__global__ void __launch_bounds__(256) k_softmax() {
    const size_t row = blockIdx.x;
    float* r = g_attn + row * NNL;
    const int tid = threadIdx.x;
    float4 v = ((float4*)r)[tid];
    __shared__ float red[8];
    float lm = fmaxf(fmaxf(v.x, v.y), fmaxf(v.z, v.w));
#pragma unroll
    for (int o = 16; o > 0; o >>= 1) lm = fmaxf(lm, __shfl_xor_sync(~0u, lm, o));
    if ((tid & 31) == 0) red[tid >> 5] = lm;
    __syncthreads();
    if (tid < 32) {
        float t = (tid < 8) ? red[tid] : -INFINITY;
#pragma unroll
        for (int o = 4; o > 0; o >>= 1) t = fmaxf(t, __shfl_xor_sync(~0u, t, o));
        if (tid == 0) red[0] = t;
    }
    __syncthreads();
    const float m = red[0];
    __syncthreads();
    v.x = expf(v.x - m); v.y = expf(v.y - m);
    v.z = expf(v.z - m); v.w = expf(v.w - m);
    float s = v.x + v.y + v.z + v.w;
#pragma unroll
    for (int o = 16; o > 0; o >>= 1) s += __shfl_xor_sync(~0u, s, o);
    if ((tid & 31) == 0) red[tid >> 5] = s;
    __syncthreads();
    if (tid < 32) {
        float t = (tid < 8) ? red[tid] : 0.f;
#pragma unroll
        for (int o = 4; o > 0; o >>= 1) t += __shfl_xor_sync(~0u, t, o);
        if (tid == 0) red[0] = t;
    }
    __syncthreads();
    const float inv = 1.f / red[0];
    v.x *= inv; v.y *= inv; v.z *= inv; v.w *= inv;
    ((float4*)r)[tid] = v;
}

// ---------------- k_av: o2[i][h*64+d] = sum_j attn[i][j] v[d][j]  (M=1024,N=64,K=1024) ---
__global__ void __launch_bounds__(256) k_av() {
    const int z = blockIdx.z;
    const int b = z >> 2, h = z & 3;
    __shared__ __nv_bfloat16 Ah[128][36], Al[128][36], Bh[64][36], Bl[64][36];
    const int tid = threadIdx.x, wid = tid >> 5, lane = tid & 31;
    const int wm = (wid >> 1) * 32, wn = (wid & 1) * 32, gr = lane >> 2, gc = lane & 3;
    const int m0 = blockIdx.x * 128;
    float acc[2][4][4] = {};
    const float* At = g_attn + (size_t)z * NNL * NNL;
    const float* V  = g_v + ((size_t)(b * PP) + h * DD) * NNL;

    for (int k0 = 0; k0 < NNL; k0 += 32) {
        ld_direct<128>(At + (size_t)m0 * NNL + k0, NNL, Ah, Al, tid);
        ld_direct<64>(V + k0, NNL, Bh, Bl, tid);
        __syncthreads();
        mma_tile<2, 4>(acc, Ah, Al, Bh, Bl, wm, wn, gr, gc);
        __syncthreads();
    }
    float* C = g_o2 + (size_t)b * NNL * PP + h * DD;
#pragma unroll
    for (int mt = 0; mt < 2; mt++)
#pragma unroll
        for (int nt = 0; nt < 4; nt++) {
            int m = m0 + wm + mt * 16 + gr;
            int n = wn + nt * 8 + gc * 2;
            *(float2*)&C[(size_t)m * PP + n]       = *(float2*)&acc[mt][nt][0];
            *(float2*)&C[(size_t)(m + 8) * PP + n] = *(float2*)&acc[mt][nt][2];
        }
}

// ---------------- LayerNorm over contiguous channels ----------------
__global__ void __launch_bounds__(256) k_ln(const float* __restrict__ lw,
                                            const float* __restrict__ lb) {
    const int row = blockIdx.x * 8 + (threadIdx.x >> 5);     // over BB*NNL rows
    const int lane = threadIdx.x & 31;
    const float* src = g_o2 + (size_t)row * PP + lane * 8;
    float* dst = g_y2 + (size_t)row * PP + lane * 8;
    float4 v0 = *(const float4*)src;
    float4 v1 = *(const float4*)(src + 4);
    float s  = v0.x + v0.y + v0.z + v0.w + v1.x + v1.y + v1.z + v1.w;
    float s2 = v0.x*v0.x + v0.y*v0.y + v0.z*v0.z + v0.w*v0.w
             + v1.x*v1.x + v1.y*v1.y + v1.z*v1.z + v1.w*v1.w;
#pragma unroll
    for (int o = 16; o > 0; o >>= 1) {
        s  += __shfl_xor_sync(~0u, s, o);
        s2 += __shfl_xor_sync(~0u, s2, o);
    }
    const float mean = s * (1.f / 256.f);
    const float var  = s2 * (1.f / 256.f) - mean * mean;
    const float rstd = rsqrtf(var + 1e-6f);
    float4 w0 = *(const float4*)(lw + lane * 8);
    float4 w1 = *(const float4*)(lw + lane * 8 + 4);
    float4 b0 = *(const float4*)(lb + lane * 8);
    float4 b1 = *(const float4*)(lb + lane * 8 + 4);
    float4 o0, o1;
    o0.x = (v0.x - mean) * rstd * w0.x + b0.x;
    o0.y = (v0.y - mean) * rstd * w0.y + b0.y;
    o0.z = (v0.z - mean) * rstd * w0.z + b0.z;
    o0.w = (v0.w - mean) * rstd * w0.w + b0.w;
    o1.x = (v1.x - mean) * rstd * w1.x + b1.x;
    o1.y = (v1.y - mean) * rstd * w1.y + b1.y;
    o1.z = (v1.z - mean) * rstd * w1.z + b1.z;
    o1.w = (v1.w - mean) * rstd * w1.w + b1.w;
    *(float4*)dst = o0;
    *(float4*)(dst + 4) = o1;
}

// ---------------- expand conv + exact GELU + residual ----------------
__global__ void __launch_bounds__(256) k_expand(const float* __restrict__ w1,
                                                const float* __restrict__ x,
                                                float* __restrict__ out) {
    const int b = blockIdx.z;
    __shared__ __nv_bfloat16 Ah[128][36], Al[128][36], Bh[128][36], Bl[128][36];
    const int tid = threadIdx.x, wid = tid >> 5, lane = tid & 31;
    const int wm = (wid >> 1) * 32, wn = (wid & 1) * 64, gr = lane >> 2, gc = lane & 3;
    const int m0 = blockIdx.y * 128, n0 = blockIdx.x * 128;
    float acc[2][8][4] = {};
    const float* Bg = g_y2 + (size_t)b * NNL * PP;

    for (int k0 = 0; k0 < PP; k0 += 32) {
        ld_direct<128>(w1 + (size_t)m0 * PP + k0, PP, Ah, Al, tid);
        ld_direct<128>(Bg + (size_t)n0 * PP + k0, PP, Bh, Bl, tid);
        __syncthreads();
        mma_tile<2, 8>(acc, Ah, Al, Bh, Bl, wm, wn, gr, gc);
        __syncthreads();
    }
    const float* xr = x + (size_t)b * INC * NNL;
    float* C = out + (size_t)b * INC * NNL;
#pragma unroll
    for (int mt = 0; mt < 2; mt++)
#pragma unroll
        for (int nt = 0; nt < 8; nt++) {
            int m = m0 + wm + mt * 16 + gr;
            int n = n0 + wn + nt * 8 + gc * 2;
#pragma unroll
            for (int half = 0; half < 2; half++) {
                int mm = m + half * 8;
                float t0 = acc[mt][nt][half * 2 + 0];
                float t1 = acc[mt][nt][half * 2 + 1];
                float2 rv;
                rv.x = t0 * normcdff(t0) + xr[(size_t)mm * NNL + n];
                rv.y = t1 * normcdff(t1) + xr[(size_t)mm * NNL + n + 1];
                *(float2*)&C[(size_t)mm * NNL + n] = rv;
            }
        }
}

// ---------------- launch ----------------
extern "C" void kernel_launch(void* const* d_in, const int* in_sizes, int n_in,
                              void* d_out, int out_size) {
    const float* x     = (const float*)d_in[0];
    const float* w_ds  = (const float*)d_in[1];
    const float* wq    = (const float*)d_in[2];
    const float* bq    = (const float*)d_in[3];
    const float* wk    = (const float*)d_in[4];
    const float* bk    = (const float*)d_in[5];
    const float* wv    = (const float*)d_in[6];
    const float* bv    = (const float*)d_in[7];
    const float* rel_h = (const float*)d_in[8];
    const float* rel_w = (const float*)d_in[9];
    const float* ln_w  = (const float*)d_in[10];
    const float* ln_b  = (const float*)d_in[11];
    const float* w1    = (const float*)d_in[12];
    float* out = (float*)d_out;

    k_pos    <<<(NHEAD * NNL * DD + 255) / 256, 256>>>(rel_h, rel_w);
    k_ds     <<<dim3(8, 2, BB), 256>>>(x, w_ds);
    k_qkv    <<<dim3(8, 2, 3 * BB), 256>>>(wq, wk, wv, bq, bk, bv);
    k_logits <<<dim3(8, 8, BB * NHEAD), 256>>>();
    k_softmax<<<BB * NHEAD * NNL, 256>>>();
    k_av     <<<dim3(8, 1, BB * NHEAD), 256>>>();
    k_ln     <<<BB * NNL / 8, 256>>>(ln_w, ln_b);
    k_expand <<<dim3(8, 8, BB), 256>>>(w1, x, out);
}